// round 16
// baseline (speedup 1.0000x reference)
#include <cuda_runtime.h>
#include <math.h>

#define BB 2
#define MM 4096
#define CC 256
#define HW 64
#define NBINS 512
#define QCAP 96
#define NPOS_MAX 169
#define PSTRH 132                 // position stride in floats (gmem AND smem)
#define DSTR 172
#define PW0 73
#define TOTPOS 7924               // 73^2 + 41^2 + 25^2 + 17^2
#define POOLBLKS (BB * 1344)

// padded pyramid: [b][half][pos][132]
__device__ __align__(1024) float g_pyr2[BB * 2 * TOTPOS * PSTRH];
__device__ int g_cnt[NBINS];
__device__ int g_qlist[NBINS * QCAP];
__device__ float g_outT[BB * MM * 324];   // [b][m][324] coalesced scratch

__constant__ int c_lvl_base[4] = {0, 5329, 7010, 7635};
__constant__ int c_lvl_pw[4]   = {73, 41, 25, 17};

// ---------------- helpers ---------------------------------------------------
__device__ __forceinline__ void fma2(unsigned long long& d, unsigned long long a,
                                     unsigned long long b) {
    asm("fma.rn.f32x2 %0, %1, %2, %0;" : "+l"(d) : "l"(a), "l"(b));
}
__device__ __forceinline__ float unpack_sum(unsigned long long v) {
    return __uint_as_float((unsigned)v) + __uint_as_float((unsigned)(v >> 32));
}
__device__ __forceinline__ void bulkcp(unsigned dst, const void* src,
                                       unsigned bytes, unsigned mbar) {
    asm volatile("cp.async.bulk.shared::cluster.global.mbarrier::complete_tx::bytes "
                 "[%0], [%1], %2, [%3];" :: "r"(dst), "l"(src), "r"(bytes), "r"(mbar)
                 : "memory");
}
__device__ __forceinline__ void mbar_init(unsigned mbar, unsigned cnt) {
    asm volatile("mbarrier.init.shared.b64 [%0], %1;" :: "r"(mbar), "r"(cnt) : "memory");
}
__device__ __forceinline__ void mbar_expect(unsigned mbar, unsigned bytes) {
    asm volatile("mbarrier.arrive.expect_tx.shared.b64 _, [%0], %1;"
                 :: "r"(mbar), "r"(bytes) : "memory");
}
__device__ __forceinline__ void mbar_wait(unsigned mbar, unsigned parity) {
    unsigned done;
    asm volatile("{\n\t.reg .pred p;\n\t"
                 "mbarrier.try_wait.parity.shared.b64 p, [%1], %2;\n\t"
                 "selp.b32 %0, 1, 0, p;\n\t}" : "=r"(done) : "r"(mbar), "r"(parity)
                 : "memory");
    while (!done)
        asm volatile("{\n\t.reg .pred p;\n\t"
                     "mbarrier.try_wait.parity.shared.b64 p, [%1], %2, 0x989680;\n\t"
                     "selp.b32 %0, 1, 0, p;\n\t}" : "=r"(done)
                     : "r"(mbar), "r"(parity) : "memory");
}

// ---------------- kernel 1: transpose + zero counters -----------------------
__global__ void transpose_kernel(const float* __restrict__ f2) {
    __shared__ float tile[32][33];
    int b = blockIdx.z, p0 = blockIdx.x * 32, c0 = blockIdx.y * 32;
    int tx = threadIdx.x, ty = threadIdx.y;
    if (blockIdx.x == 0 && blockIdx.y == 0 && blockIdx.z == 0) {
        int t = ty * 32 + tx;
        if (t < NBINS) g_cnt[t] = 0;
    }
    tile[ty][tx] = f2[((size_t)b * CC + (c0 + ty)) * (HW * HW) + p0 + tx];
    __syncthreads();
    int p = p0 + ty, y = p >> 6, x = p & 63;
    int c = c0 + tx, h = c >> 7, cc = c & 127;
    int pos = (y + 4) * PW0 + (x + 4);
    g_pyr2[((size_t)(b * 2 + h) * TOTPOS + pos) * PSTRH + cc] = tile[tx][ty];
}

// ---------------- kernel 2: pooled levels + histogram + halo zero (fused) ---
__global__ void pool_hist_kernel(const float* __restrict__ cen) {
    int r = blockIdx.x;
    if (r < POOLBLKS) {
        int b = r / 1344, t = r - b * 1344;
        int l, W, i;
        if (t < 1024)      { l = 1; W = 32; i = t; }
        else if (t < 1280) { l = 2; W = 16; i = t - 1024; }
        else               { l = 3; W = 8;  i = t - 1280; }
        int y = i / W, x = i - (i / W) * W;
        int S = 1 << l;
        int c = threadIdx.x;
        int h = c >> 7, cc = c & 127;
        const float* in = g_pyr2 + (size_t)(b * 2 + h) * TOTPOS * PSTRH + cc;
        float s = 0.f;
        for (int dy = 0; dy < S; dy++)
            for (int dx = 0; dx < S; dx++)
                s += in[(size_t)((y * S + dy + 4) * PW0 + (x * S + dx + 4)) * PSTRH];
        g_pyr2[((size_t)(b * 2 + h) * TOTPOS + c_lvl_base[l]
                + (y + 4) * c_lvl_pw[l] + (x + 4)) * PSTRH + cc] = s / (float)(S * S);
    } else {
        int t = (r - POOLBLKS) * blockDim.x + threadIdx.x;

        for (int p = t; p < BB * 2 * TOTPOS; p += 32 * 256) {
            int pp = p % TOTPOS;
            int l = pp < 5329 ? 0 : (pp < 7010 ? 1 : (pp < 7635 ? 2 : 3));
            int pwl = c_lvl_pw[l];
            int rr = pp - c_lvl_base[l];
            int y = rr / pwl, x = rr - (rr / pwl) * pwl;
            int W = pwl - 9;
            if (x < 4 || x >= W + 4 || y < 4 || y >= W + 4) {
                float4* dst = (float4*)(g_pyr2 + (size_t)p * PSTRH);
                #pragma unroll 4
                for (int i = 0; i < PSTRH / 4; i++)
                    dst[i] = make_float4(0.f, 0.f, 0.f, 0.f);
            }
        }

        if (t < BB * MM) {
            float cx = cen[2 * t], cy = cen[2 * t + 1];
            int bx = ((int)cx) >> 2;  bx = bx < 0 ? 0 : (bx > 15 ? 15 : bx);
            int by = ((int)cy) >> 2;  by = by < 0 ? 0 : (by > 15 ? 15 : by);
            int b = t / MM, m = t - b * MM;
            int bin = (b << 8) | (by << 4) | bx;
            int pos = atomicAdd(&g_cnt[bin], 1);
            if (pos < QCAP) g_qlist[bin * QCAP + pos] = m;
        }
    }
}

// ---------------- GEMM inner loop: 4q x 4 strips (32 pos) per warp ----------
template <int NQI>
__device__ __forceinline__ void gemm_half(const float* __restrict__ As,
                                          const float* __restrict__ Ps,
                                          int qsel, const int* poff,
                                          unsigned long long acc[4][4]) {
    #pragma unroll 2
    for (int c = 0; c < 128; c += 4) {
        ulonglong2 a[NQI], p[4];
        #pragma unroll
        for (int qi = 0; qi < NQI; qi++)
            a[qi] = *(const ulonglong2*)&As[(qsel + 4 * qi) * PSTRH + c];
        #pragma unroll
        for (int pi = 0; pi < 4; pi++)
            p[pi] = *(const ulonglong2*)&Ps[poff[pi] + c];
        #pragma unroll
        for (int qi = 0; qi < NQI; qi++)
            #pragma unroll
            for (int pi = 0; pi < 4; pi++) {
                fma2(acc[qi][pi], a[qi].x, p[pi].x);
                fma2(acc[qi][pi], a[qi].y, p[pi].y);
            }
    }
}

__global__ __launch_bounds__(256, 2) void corr_kernel(const float* __restrict__ f1,
                                                      const float* __restrict__ cen) {
    extern __shared__ float sm[];
    float* Ps = sm;                           // 169*132
    float* As = sm + NPOS_MAX * PSTRH;        // 16*132
    float* Ds = As + 16 * PSTRH;              // 16*172
    __shared__ __align__(8) unsigned long long mbar_s;

    int blk = blockIdx.x;
    int chunk = blk >> 11;                    // 0 or 1
    int rest = blk & 2047;
    int lvl = rest >> 9, bin = rest & 511;    // LPT: all L0 items first
    int b = bin >> 8, by = (bin >> 4) & 15, bx = bin & 15;
    int nq = g_cnt[bin]; if (nq > QCAP) nq = QCAP;
    if (nq <= 16 * chunk) return;             // chunk-1 blocks exit if nq <= 16

    int ixmin = (4 * bx) >> lvl, ixmax = (4 * bx + 3) >> lvl;
    int iymin = (4 * by) >> lvl, iymax = (4 * by + 3) >> lvl;
    int px0 = ixmin - 4, py0 = iymin - 4;
    int pw = ixmax - ixmin + 10, ph = iymax - iymin + 10;
    int Npos = pw * ph;
    int pwp = c_lvl_pw[lvl];

    int tid = threadIdx.x, lane = tid & 31, w = tid >> 5;
    int qsel = lane >> 3, psel = lane & 7;
    int wbase = w * 32;
    bool act = wbase < Npos;
    float scale = 1.0f / (float)(1 << lvl);

    unsigned Ps_b = (unsigned)__cvta_generic_to_shared(Ps);
    unsigned As_b = (unsigned)__cvta_generic_to_shared(As);
    unsigned mbar = (unsigned)__cvta_generic_to_shared(&mbar_s);

    if (tid == 0) mbar_init(mbar, 1);
    __syncthreads();
    unsigned par = 0;

    int poff[4];
    #pragma unroll
    for (int pi = 0; pi < 4; pi++) {
        int p = wbase + psel + 8 * pi;
        poff[pi] = ((p < Npos) ? p : (Npos - 1)) * PSTRH;
    }

    unsigned rowB = (unsigned)(pw * PSTRH * 4);   // bytes per contiguous patch row

    for (int q0 = 16 * chunk; q0 < nq; q0 += 32) {
        int qcnt = nq - q0; if (qcnt > 16) qcnt = 16;
        int nqi = (qcnt + 3) >> 2;            // 1..4, uniform across warps

        unsigned long long acc[4][4];
        #pragma unroll
        for (int qi = 0; qi < 4; qi++)
            #pragma unroll
            for (int pi = 0; pi < 4; pi++) acc[qi][pi] = 0ull;

        for (int h = 0; h < 2; h++) {
            __syncthreads();   // previous phase's smem fully consumed
            if (tid == 0)
                mbar_expect(mbar, (unsigned)Npos * (PSTRH * 4u)
                                  + (unsigned)qcnt * 512u);

            const float* pbase = g_pyr2
                + ((size_t)(b * 2 + h) * TOTPOS + c_lvl_base[lvl]
                   + (size_t)(py0 + 4) * pwp + (px0 + 4)) * PSTRH;
            // row-granular patch staging: ph ops of pw*528 B (contiguous both sides)
            if (tid < ph) {
                bulkcp(Ps_b + (unsigned)(tid * pw * PSTRH) * 4u,
                       pbase + (size_t)tid * pwp * PSTRH, rowB, mbar);
            } else if (tid < ph + qcnt) {
                int qq = tid - ph;
                int m = g_qlist[bin * QCAP + q0 + qq];
                bulkcp(As_b + (unsigned)(qq * PSTRH) * 4u,
                       f1 + ((size_t)b * MM + m) * CC + h * 128, 512u, mbar);
            }
            mbar_wait(mbar, par);
            par ^= 1;

            if (act) {
                switch (nqi) {
                    case 4: gemm_half<4>(As, Ps, qsel, poff, acc); break;
                    case 3: gemm_half<3>(As, Ps, qsel, poff, acc); break;
                    case 2: gemm_half<2>(As, Ps, qsel, poff, acc); break;
                    default: gemm_half<1>(As, Ps, qsel, poff, acc); break;
                }
            }
        }

        // ---- write D -------------------------------------------------------
        if (act) {
            #pragma unroll
            for (int pi = 0; pi < 4; pi++) {
                int p = wbase + psel + 8 * pi;
                if (p < Npos) {
                    #pragma unroll
                    for (int qi = 0; qi < 4; qi++)
                        Ds[(qsel + 4 * qi) * DSTR + p] = unpack_sum(acc[qi][pi]);
                }
            }
        }
        __syncthreads();

        // ---- bilinear epilogue: warp per query, coalesced scratch writes ---
        for (int qq = w; qq < qcnt; qq += 8) {
            int m = g_qlist[bin * QCAP + q0 + qq];
            float cx = cen[((size_t)b * MM + m) * 2 + 0];
            float cy = cen[((size_t)b * MM + m) * 2 + 1];
            float sx = cx * scale, sy = cy * scale;
            float fix = floorf(sx), fiy = floorf(sy);
            float fx = sx - fix, fy = sy - fiy;
            int ox = (int)fix - 4 - px0;
            int oy = (int)fiy - 4 - py0;
            float wx1 = fx, wx0 = 1.f - fx, wy1 = fy, wy0 = 1.f - fy;
            const float* Dq = Ds + qq * DSTR;
            float* dst = g_outT + ((size_t)b * MM + m) * 324 + lvl * 81;
            for (int e = lane; e < 81; e += 32) {
                int i = e / 9, j = e - (e / 9) * 9;
                int base = (oy + j) * pw + (ox + i);
                float d00 = Dq[base],      d01 = Dq[base + 1];
                float d10 = Dq[base + pw], d11 = Dq[base + pw + 1];
                dst[e] = wy0 * (wx0 * d00 + wx1 * d01)
                       + wy1 * (wx0 * d10 + wx1 * d11);
            }
        }
    }
}

// ---------------- kernel 5: transpose scratch -> out (B, 324, M) ------------
// One block per 32-m strip: load 32 x 324 floats (coalesced over e, padded
// smem stride 325 -> conflict-free both phases), store warp-per-e-row with
// lanes sweeping m (128 B contiguous STG). No partial tiles.
__global__ __launch_bounds__(256, 2) void out_transpose_kernel(float* __restrict__ out) {
    __shared__ float tile[32][325];
    int b = blockIdx.y;
    int m0 = blockIdx.x * 32;
    int tid = threadIdx.x, lane = tid & 31, w = tid >> 5;

    const float* src = g_outT + ((size_t)b * MM + m0) * 324;
    for (int i = tid; i < 32 * 324; i += 256) {
        int m = i / 324, e = i - m * 324;
        tile[m][e] = src[m * 324 + e];
    }
    __syncthreads();
    for (int e = w; e < 324; e += 8)
        out[((size_t)b * 324 + e) * MM + m0 + lane] = tile[lane][e];
}

// ---------------- launch ----------------------------------------------------
extern "C" void kernel_launch(void* const* d_in, const int* in_sizes, int n_in,
                              void* d_out, int out_size) {
    const float* f1  = (const float*)d_in[0];
    const float* f2  = (const float*)d_in[1];
    const float* cen = (const float*)d_in[2];
    float* out = (float*)d_out;

    size_t smem = (size_t)(NPOS_MAX * PSTRH + 16 * PSTRH + 16 * DSTR) * sizeof(float);
    cudaFuncSetAttribute(corr_kernel, cudaFuncAttributeMaxDynamicSharedMemorySize,
                         (int)smem);

    transpose_kernel<<<dim3(HW * HW / 32, CC / 32, BB), dim3(32, 32)>>>(f2);
    pool_hist_kernel<<<POOLBLKS + 32, 256>>>(cen);
    corr_kernel<<<NBINS * 4 * 2, 256, smem>>>(f1, cen);
    out_transpose_kernel<<<dim3(MM / 32, BB), 256>>>(out);
}

// round 17
// speedup vs baseline: 1.0398x; 1.0398x over previous
#include <cuda_runtime.h>
#include <math.h>

#define BB 2
#define MM 4096
#define CC 256
#define HW 64
#define NBINS 512
#define QCAP 96
#define NPOS_MAX 169
#define PSTRH 132                 // position stride in floats (gmem AND smem)
#define DSTR 172
#define PW0 73
#define TOTPOS 7924               // 73^2 + 41^2 + 25^2 + 17^2
#define POOLBLKS (BB * 1344)

// padded pyramid: [b][half][pos][132]
__device__ __align__(1024) float g_pyr2[BB * 2 * TOTPOS * PSTRH];
__device__ int g_cnt[NBINS];
__device__ int g_qlist[NBINS * QCAP];
__device__ float g_outT[BB * MM * 324];   // [b][m][324] coalesced scratch

__constant__ int c_lvl_base[4] = {0, 5329, 7010, 7635};
__constant__ int c_lvl_pw[4]   = {73, 41, 25, 17};

// ---------------- helpers ---------------------------------------------------
__device__ __forceinline__ void fma2(unsigned long long& d, unsigned long long a,
                                     unsigned long long b) {
    asm("fma.rn.f32x2 %0, %1, %2, %0;" : "+l"(d) : "l"(a), "l"(b));
}
__device__ __forceinline__ float unpack_sum(unsigned long long v) {
    return __uint_as_float((unsigned)v) + __uint_as_float((unsigned)(v >> 32));
}
__device__ __forceinline__ void bulkcp(unsigned dst, const void* src,
                                       unsigned bytes, unsigned mbar) {
    asm volatile("cp.async.bulk.shared::cluster.global.mbarrier::complete_tx::bytes "
                 "[%0], [%1], %2, [%3];" :: "r"(dst), "l"(src), "r"(bytes), "r"(mbar)
                 : "memory");
}
__device__ __forceinline__ void mbar_init(unsigned mbar, unsigned cnt) {
    asm volatile("mbarrier.init.shared.b64 [%0], %1;" :: "r"(mbar), "r"(cnt) : "memory");
}
__device__ __forceinline__ void mbar_expect(unsigned mbar, unsigned bytes) {
    asm volatile("mbarrier.arrive.expect_tx.shared.b64 _, [%0], %1;"
                 :: "r"(mbar), "r"(bytes) : "memory");
}
__device__ __forceinline__ void mbar_wait(unsigned mbar, unsigned parity) {
    unsigned done;
    asm volatile("{\n\t.reg .pred p;\n\t"
                 "mbarrier.try_wait.parity.shared.b64 p, [%1], %2;\n\t"
                 "selp.b32 %0, 1, 0, p;\n\t}" : "=r"(done) : "r"(mbar), "r"(parity)
                 : "memory");
    while (!done)
        asm volatile("{\n\t.reg .pred p;\n\t"
                     "mbarrier.try_wait.parity.shared.b64 p, [%1], %2, 0x989680;\n\t"
                     "selp.b32 %0, 1, 0, p;\n\t}" : "=r"(done)
                     : "r"(mbar), "r"(parity) : "memory");
}

// ---------------- kernel 1: transpose + zero counters -----------------------
__global__ void transpose_kernel(const float* __restrict__ f2) {
    __shared__ float tile[32][33];
    int b = blockIdx.z, p0 = blockIdx.x * 32, c0 = blockIdx.y * 32;
    int tx = threadIdx.x, ty = threadIdx.y;
    if (blockIdx.x == 0 && blockIdx.y == 0 && blockIdx.z == 0) {
        int t = ty * 32 + tx;
        if (t < NBINS) g_cnt[t] = 0;
    }
    tile[ty][tx] = f2[((size_t)b * CC + (c0 + ty)) * (HW * HW) + p0 + tx];
    __syncthreads();
    int p = p0 + ty, y = p >> 6, x = p & 63;
    int c = c0 + tx, h = c >> 7, cc = c & 127;
    int pos = (y + 4) * PW0 + (x + 4);
    g_pyr2[((size_t)(b * 2 + h) * TOTPOS + pos) * PSTRH + cc] = tile[tx][ty];
}

// ---------------- kernel 2: pooled levels + histogram + halo zero (fused) ---
__global__ void pool_hist_kernel(const float* __restrict__ cen) {
    int r = blockIdx.x;
    if (r < POOLBLKS) {
        int b = r / 1344, t = r - b * 1344;
        int l, W, i;
        if (t < 1024)      { l = 1; W = 32; i = t; }
        else if (t < 1280) { l = 2; W = 16; i = t - 1024; }
        else               { l = 3; W = 8;  i = t - 1280; }
        int y = i / W, x = i - (i / W) * W;
        int S = 1 << l;
        int c = threadIdx.x;
        int h = c >> 7, cc = c & 127;
        const float* in = g_pyr2 + (size_t)(b * 2 + h) * TOTPOS * PSTRH + cc;
        float s = 0.f;
        for (int dy = 0; dy < S; dy++)
            for (int dx = 0; dx < S; dx++)
                s += in[(size_t)((y * S + dy + 4) * PW0 + (x * S + dx + 4)) * PSTRH];
        g_pyr2[((size_t)(b * 2 + h) * TOTPOS + c_lvl_base[l]
                + (y + 4) * c_lvl_pw[l] + (x + 4)) * PSTRH + cc] = s / (float)(S * S);
    } else {
        int t = (r - POOLBLKS) * blockDim.x + threadIdx.x;

        for (int p = t; p < BB * 2 * TOTPOS; p += 32 * 256) {
            int pp = p % TOTPOS;
            int l = pp < 5329 ? 0 : (pp < 7010 ? 1 : (pp < 7635 ? 2 : 3));
            int pwl = c_lvl_pw[l];
            int rr = pp - c_lvl_base[l];
            int y = rr / pwl, x = rr - (rr / pwl) * pwl;
            int W = pwl - 9;
            if (x < 4 || x >= W + 4 || y < 4 || y >= W + 4) {
                float4* dst = (float4*)(g_pyr2 + (size_t)p * PSTRH);
                #pragma unroll 4
                for (int i = 0; i < PSTRH / 4; i++)
                    dst[i] = make_float4(0.f, 0.f, 0.f, 0.f);
            }
        }

        if (t < BB * MM) {
            float cx = cen[2 * t], cy = cen[2 * t + 1];
            int bx = ((int)cx) >> 2;  bx = bx < 0 ? 0 : (bx > 15 ? 15 : bx);
            int by = ((int)cy) >> 2;  by = by < 0 ? 0 : (by > 15 ? 15 : by);
            int b = t / MM, m = t - b * MM;
            int bin = (b << 8) | (by << 4) | bx;
            int pos = atomicAdd(&g_cnt[bin], 1);
            if (pos < QCAP) g_qlist[bin * QCAP + pos] = m;
        }
    }
}

// ---------------- GEMM inner loop: 4q x 4 strips (32 pos) per warp ----------
template <int NQI>
__device__ __forceinline__ void gemm_half(const float* __restrict__ As,
                                          const float* __restrict__ Ps,
                                          int qsel, const int* poff,
                                          unsigned long long acc[4][4]) {
    #pragma unroll 2
    for (int c = 0; c < 128; c += 4) {
        ulonglong2 a[NQI], p[4];
        #pragma unroll
        for (int qi = 0; qi < NQI; qi++)
            a[qi] = *(const ulonglong2*)&As[(qsel + 4 * qi) * PSTRH + c];
        #pragma unroll
        for (int pi = 0; pi < 4; pi++)
            p[pi] = *(const ulonglong2*)&Ps[poff[pi] + c];
        #pragma unroll
        for (int qi = 0; qi < NQI; qi++)
            #pragma unroll
            for (int pi = 0; pi < 4; pi++) {
                fma2(acc[qi][pi], a[qi].x, p[pi].x);
                fma2(acc[qi][pi], a[qi].y, p[pi].y);
            }
    }
}

__global__ __launch_bounds__(256, 2) void corr_kernel(const float* __restrict__ f1,
                                                      const float* __restrict__ cen) {
    extern __shared__ float sm[];
    float* Ps = sm;                           // 169*132
    float* As = sm + NPOS_MAX * PSTRH;        // 16*132
    float* Ds = As + 16 * PSTRH;              // 16*172
    __shared__ __align__(8) unsigned long long mbar_s;

    int blk = blockIdx.x;
    int chunk = blk >> 11;                    // 0 or 1
    int rest = blk & 2047;
    int lvl = rest >> 9, bin = rest & 511;    // LPT: all L0 items first
    int b = bin >> 8, by = (bin >> 4) & 15, bx = bin & 15;
    int nq = g_cnt[bin]; if (nq > QCAP) nq = QCAP;
    if (nq <= 16 * chunk) return;             // chunk-1 blocks exit if nq <= 16

    int ixmin = (4 * bx) >> lvl, ixmax = (4 * bx + 3) >> lvl;
    int iymin = (4 * by) >> lvl, iymax = (4 * by + 3) >> lvl;
    int px0 = ixmin - 4, py0 = iymin - 4;
    int pw = ixmax - ixmin + 10, ph = iymax - iymin + 10;
    int Npos = pw * ph;
    int pwp = c_lvl_pw[lvl];

    int tid = threadIdx.x, lane = tid & 31, w = tid >> 5;
    int qsel = lane >> 3, psel = lane & 7;
    int wbase = w * 32;
    bool act = wbase < Npos;
    float scale = 1.0f / (float)(1 << lvl);

    unsigned Ps_b = (unsigned)__cvta_generic_to_shared(Ps);
    unsigned As_b = (unsigned)__cvta_generic_to_shared(As);
    unsigned mbar = (unsigned)__cvta_generic_to_shared(&mbar_s);

    if (tid == 0) mbar_init(mbar, 1);
    __syncthreads();
    unsigned par = 0;

    int poff[4];
    #pragma unroll
    for (int pi = 0; pi < 4; pi++) {
        int p = wbase + psel + 8 * pi;
        poff[pi] = ((p < Npos) ? p : (Npos - 1)) * PSTRH;
    }

    unsigned rowB = (unsigned)(pw * PSTRH * 4);   // bytes per contiguous patch row

    for (int q0 = 16 * chunk; q0 < nq; q0 += 32) {
        int qcnt = nq - q0; if (qcnt > 16) qcnt = 16;
        int nqi = (qcnt + 3) >> 2;            // 1..4, uniform across warps

        unsigned long long acc[4][4];
        #pragma unroll
        for (int qi = 0; qi < 4; qi++)
            #pragma unroll
            for (int pi = 0; pi < 4; pi++) acc[qi][pi] = 0ull;

        for (int h = 0; h < 2; h++) {
            __syncthreads();   // previous phase's smem fully consumed
            if (tid == 0)
                mbar_expect(mbar, (unsigned)Npos * (PSTRH * 4u)
                                  + (unsigned)qcnt * 512u);

            const float* pbase = g_pyr2
                + ((size_t)(b * 2 + h) * TOTPOS + c_lvl_base[lvl]
                   + (size_t)(py0 + 4) * pwp + (px0 + 4)) * PSTRH;
            // row-granular patch staging: ph ops of pw*528 B (contiguous both sides)
            if (tid < ph) {
                bulkcp(Ps_b + (unsigned)(tid * pw * PSTRH) * 4u,
                       pbase + (size_t)tid * pwp * PSTRH, rowB, mbar);
            } else if (tid < ph + qcnt) {
                int qq = tid - ph;
                int m = g_qlist[bin * QCAP + q0 + qq];
                bulkcp(As_b + (unsigned)(qq * PSTRH) * 4u,
                       f1 + ((size_t)b * MM + m) * CC + h * 128, 512u, mbar);
            }
            mbar_wait(mbar, par);
            par ^= 1;

            if (act) {
                switch (nqi) {
                    case 4: gemm_half<4>(As, Ps, qsel, poff, acc); break;
                    case 3: gemm_half<3>(As, Ps, qsel, poff, acc); break;
                    case 2: gemm_half<2>(As, Ps, qsel, poff, acc); break;
                    default: gemm_half<1>(As, Ps, qsel, poff, acc); break;
                }
            }
        }

        // ---- write D -------------------------------------------------------
        if (act) {
            #pragma unroll
            for (int pi = 0; pi < 4; pi++) {
                int p = wbase + psel + 8 * pi;
                if (p < Npos) {
                    #pragma unroll
                    for (int qi = 0; qi < 4; qi++)
                        Ds[(qsel + 4 * qi) * DSTR + p] = unpack_sum(acc[qi][pi]);
                }
            }
        }
        __syncthreads();

        // ---- bilinear epilogue: warp per query, coalesced scratch writes ---
        for (int qq = w; qq < qcnt; qq += 8) {
            int m = g_qlist[bin * QCAP + q0 + qq];
            float cx = cen[((size_t)b * MM + m) * 2 + 0];
            float cy = cen[((size_t)b * MM + m) * 2 + 1];
            float sx = cx * scale, sy = cy * scale;
            float fix = floorf(sx), fiy = floorf(sy);
            float fx = sx - fix, fy = sy - fiy;
            int ox = (int)fix - 4 - px0;
            int oy = (int)fiy - 4 - py0;
            float wx1 = fx, wx0 = 1.f - fx, wy1 = fy, wy0 = 1.f - fy;
            const float* Dq = Ds + qq * DSTR;
            float* dst = g_outT + ((size_t)b * MM + m) * 324 + lvl * 81;
            for (int e = lane; e < 81; e += 32) {
                int i = e / 9, j = e - (e / 9) * 9;
                int base = (oy + j) * pw + (ox + i);
                float d00 = Dq[base],      d01 = Dq[base + 1];
                float d10 = Dq[base + pw], d11 = Dq[base + pw + 1];
                dst[e] = wy0 * (wx0 * d00 + wx1 * d01)
                       + wy1 * (wx0 * d10 + wx1 * d11);
            }
        }
    }
}

// ---------------- kernel 5: transpose scratch -> out (B, 324, M) ------------
// Block = (32-m strip) x (81-e level chunk). 10.4 KB smem -> high occupancy.
// tile[32][81]: 81 mod 32 = 17, gcd(17,32)=1 -> both phases conflict-free.
// Load lanes sweep contiguous e; store lanes sweep contiguous m.
__global__ __launch_bounds__(256) void out_transpose_kernel(float* __restrict__ out) {
    __shared__ float tile[32][81];
    int b = blockIdx.z;
    int e0 = blockIdx.y * 81;
    int m0 = blockIdx.x * 32;
    int tid = threadIdx.x, lane = tid & 31, w = tid >> 5;

    const float* src = g_outT + ((size_t)b * MM + m0) * 324 + e0;
    for (int i = tid; i < 32 * 81; i += 256) {
        int m = i / 81, e = i - m * 81;
        tile[m][e] = src[(size_t)m * 324 + e];
    }
    __syncthreads();
    for (int e = w; e < 81; e += 8)
        out[((size_t)b * 324 + e0 + e) * MM + m0 + lane] = tile[lane][e];
}

// ---------------- launch ----------------------------------------------------
extern "C" void kernel_launch(void* const* d_in, const int* in_sizes, int n_in,
                              void* d_out, int out_size) {
    const float* f1  = (const float*)d_in[0];
    const float* f2  = (const float*)d_in[1];
    const float* cen = (const float*)d_in[2];
    float* out = (float*)d_out;

    size_t smem = (size_t)(NPOS_MAX * PSTRH + 16 * PSTRH + 16 * DSTR) * sizeof(float);
    cudaFuncSetAttribute(corr_kernel, cudaFuncAttributeMaxDynamicSharedMemorySize,
                         (int)smem);

    transpose_kernel<<<dim3(HW * HW / 32, CC / 32, BB), dim3(32, 32)>>>(f2);
    pool_hist_kernel<<<POOLBLKS + 32, 256>>>(cen);
    corr_kernel<<<NBINS * 4 * 2, 256, smem>>>(f1, cen);
    out_transpose_kernel<<<dim3(MM / 32, 4, BB), 256>>>(out);
}